// round 9
// baseline (speedup 1.0000x reference)
#include <cuda_runtime.h>
#include <cuda_bf16.h>
#include <math.h>

#define HW 200704
#define CC 192
#define NHEAD 6
#define TSS 197

// ---------------- scratch ----------------
__device__ float g_mu[HW];
__device__ float g_rstd[HW];
__device__ float g_Wf[576 * CC];
__device__ float g_bias[576];
__device__ float g_G[CC * CC];
__device__ float g_s[CC];
__device__ float g_T[384 * CC];
__device__ float g_u[384];
__device__ __align__(16) __nv_bfloat16 g_Wvb[CC * CC];   // v rows of folded weight, bf16
__device__ __align__(16) __nv_bfloat16 g_Wpb[CC * CC];   // proj_w bf16
__device__ __align__(16) __nv_bfloat16 g_gmc[CC * 32];   // per-head gm blocks, compact [192][32]

// ---------------- mma helper ----------------
__device__ __forceinline__ void mma16816(float* c, const unsigned* a, const unsigned* b) {
    asm volatile(
        "mma.sync.aligned.m16n8k16.row.col.f32.bf16.bf16.f32 "
        "{%0,%1,%2,%3},{%4,%5,%6,%7},{%8,%9},{%0,%1,%2,%3};\n"
        : "+f"(c[0]), "+f"(c[1]), "+f"(c[2]), "+f"(c[3])
        : "r"(a[0]), "r"(a[1]), "r"(a[2]), "r"(a[3]), "r"(b[0]), "r"(b[1]));
}

// ---------------- LN stats + zero accumulators + proj_w bf16 convert -------------
__global__ void k_stats(const float* __restrict__ x, const float* __restrict__ proj_w) {
    int i = blockIdx.x * 256 + threadIdx.x;
    if (i < CC * CC) { g_G[i] = 0.f; g_Wpb[i] = __float2bfloat16(proj_w[i]); }
    if (i < CC) g_s[i] = 0.f;
    int p = i;
    float s = 0.f, ss = 0.f;
#pragma unroll 8
    for (int c = 0; c < CC; c++) {
        float v = x[c * HW + p];
        s += v; ss += v * v;
    }
    float mu  = s * (1.f / CC);
    float var = ss * (1.f / CC) - mu * mu;
    g_mu[p]   = mu;
    g_rstd[p] = rsqrtf(var + 1e-5f);
}

// ---------------- fold weights ----------------
__global__ void k_fold(const float* __restrict__ qkv_w, const float* __restrict__ pre_w,
                       const float* __restrict__ ln_g, const float* __restrict__ ln_b,
                       const float* __restrict__ pre_b) {
    int o = blockIdx.x, j = threadIdx.x;
    float w2 = 0.f;
#pragma unroll 4
    for (int c = 0; c < CC; c++) w2 += qkv_w[o * CC + c] * pre_w[c * CC + j];
    float wf = w2 * ln_g[j];
    g_Wf[o * CC + j] = wf;
    if (o >= 384) g_Wvb[(o - 384) * CC + j] = __float2bfloat16(wf);
    __shared__ float s2[CC];
    s2[j] = w2 * ln_b[j] + qkv_w[o * CC + j] * pre_b[j];
    __syncthreads();
    if (j < 64) s2[j] += s2[j + 64] + s2[j + 128];
    __syncthreads();
    if (j < 32) {
        float b = s2[j] + s2[j + 32];
#pragma unroll
        for (int off = 16; off > 0; off >>= 1) b += __shfl_down_sync(0xffffffffu, b, off);
        if (j == 0) g_bias[o] = b;
    }
}

// ---------------- Gram of xhat: split halves (2 CTAs/SM), 64-pixel tiles ---------
#define NT64 (HW / 64)
__global__ __launch_bounds__(256) void k_gram(const float* __restrict__ x) {
    extern __shared__ __align__(16) unsigned short xs[];   // [2][CC][72]
    int tid = threadIdx.x;
    int warp = tid >> 5, lane = tid & 31, gid = lane >> 2, tig = lane & 3;
    int nsel = blockIdx.x & 1;
    int m0 = (warp & 3) * 48;
    int n0 = nsel * 96 + (warp >> 2) * 48;
    float acc[3][6][4];
#pragma unroll
    for (int f = 0; f < 3; f++)
#pragma unroll
        for (int g = 0; g < 6; g++)
#pragma unroll
            for (int r = 0; r < 4; r++) acc[f][g][r] = 0.f;
    float srow[12];
#pragma unroll
    for (int i = 0; i < 12; i++) srow[i] = 0.f;

    auto load_half = [&](int t, int b, int h) {
        int p0 = t * 64;
#pragma unroll
        for (int i = 0; i < 6; i++) {
            int q = tid + 256 * (h * 6 + i);
            int c = q >> 4, seg = q & 15;
            int p = p0 + seg * 4;
            float4 xv = *(const float4*)(x + c * HW + p);
            float4 m4 = *(const float4*)(g_mu + p);
            float4 r4 = *(const float4*)(g_rstd + p);
            float h0 = (xv.x - m4.x) * r4.x;
            float h1 = (xv.y - m4.y) * r4.y;
            float h2 = (xv.z - m4.z) * r4.z;
            float h3 = (xv.w - m4.w) * r4.w;
            __nv_bfloat162 lo = __floats2bfloat162_rn(h0, h1);
            __nv_bfloat162 hi = __floats2bfloat162_rn(h2, h3);
            uint2 u;
            u.x = *(unsigned*)&lo;
            u.y = *(unsigned*)&hi;
            *(uint2*)(xs + (b * CC + c) * 72 + seg * 4) = u;
            if (nsel == 0) srow[h * 6 + i] += h0 + h1 + h2 + h3;
        }
    };

    int t = blockIdx.x >> 1;
    int step = gridDim.x >> 1;
    int iter = 0;
    load_half(t, 0, 0);
    load_half(t, 0, 1);
    __syncthreads();
    while (t < NT64) {
        int b = iter & 1;
        int tn = t + step;
        if (tn < NT64) { load_half(tn, b ^ 1, 0); load_half(tn, b ^ 1, 1); }
#pragma unroll
        for (int ks = 0; ks < 4; ks++) {
            int kl = ks * 16 + 2 * tig;
            unsigned a[3][4];
#pragma unroll
            for (int f = 0; f < 3; f++) {
                int r = m0 + f * 16 + gid;
                a[f][0] = *(const unsigned*)&xs[(b * CC + r) * 72 + kl];
                a[f][1] = *(const unsigned*)&xs[(b * CC + r + 8) * 72 + kl];
                a[f][2] = *(const unsigned*)&xs[(b * CC + r) * 72 + kl + 8];
                a[f][3] = *(const unsigned*)&xs[(b * CC + r + 8) * 72 + kl + 8];
            }
#pragma unroll
            for (int g = 0; g < 6; g++) {
                int n = n0 + g * 8 + gid;
                unsigned bb[2];
                bb[0] = *(const unsigned*)&xs[(b * CC + n) * 72 + kl];
                bb[1] = *(const unsigned*)&xs[(b * CC + n) * 72 + kl + 8];
#pragma unroll
                for (int f = 0; f < 3; f++) mma16816(acc[f][g], a[f], bb);
            }
        }
        __syncthreads();
        t = tn; iter++;
    }
#pragma unroll
    for (int f = 0; f < 3; f++) {
        int m = m0 + f * 16 + gid;
#pragma unroll
        for (int g = 0; g < 6; g++) {
            int n = n0 + g * 8 + 2 * tig;
            atomicAdd(&g_G[m * CC + n],           acc[f][g][0]);
            atomicAdd(&g_G[m * CC + n + 1],       acc[f][g][1]);
            atomicAdd(&g_G[(m + 8) * CC + n],     acc[f][g][2]);
            atomicAdd(&g_G[(m + 8) * CC + n + 1], acc[f][g][3]);
        }
    }
    if (nsel == 0) {
#pragma unroll
        for (int i = 0; i < 12; i++) atomicAdd(&g_s[(tid + 256 * i) >> 4], srow[i]);
    }
}

// ---------------- T = W_{q,k} @ G ; u = W_{q,k} @ s (parallel, 384 blocks) -------
__global__ void k_T() {
    int o = blockIdx.x, j = threadIdx.x;
    float acc = 0.f;
#pragma unroll 4
    for (int c = 0; c < CC; c++) acc += g_Wf[o * CC + c] * g_G[c * CC + j];
    g_T[o * CC + j] = acc;
    __shared__ float sh[CC];
    sh[j] = g_Wf[o * CC + j] * g_s[j];
    __syncthreads();
    if (j < 64) sh[j] += sh[j + 64] + sh[j + 128];
    __syncthreads();
    if (j < 32) {
        float a = sh[j] + sh[j + 32];
#pragma unroll
        for (int off = 16; off > 0; off >>= 1) a += __shfl_down_sync(0xffffffffu, a, off);
        if (j == 0) g_u[o] = a;
    }
}

// ---------------- attn -> mn -> gating -> gm (compact bf16) ----------------
__global__ __launch_bounds__(1024) void k_gm(const float* __restrict__ mn_w,
                                             const float* __restrict__ gating) {
    int h = blockIdx.x, tid = threadIdx.x;
    int d = tid >> 5, e = tid & 31;
    __shared__ float attn[32][33];
    __shared__ float nq[32], nk[32];
    if (tid < 64) {
        int o = (tid < 32) ? (h * 32 + tid) : (CC + h * 32 + (tid - 32));
        float acc = 0.f;
        for (int c2 = 0; c2 < CC; c2++) acc += g_T[o * CC + c2] * g_Wf[o * CC + c2];
        float b = g_bias[o];
        acc += 2.f * b * g_u[o] + (float)HW * b * b;
        float nval = fmaxf(sqrtf(fmaxf(acc, 0.f)), 1e-12f);
        if (tid < 32) nq[tid] = nval; else nk[tid - 32] = nval;
    }
    __syncthreads();
    int oq = h * 32 + d, ok = CC + h * 32 + e;
    float acc = 0.f;
    for (int c2 = 0; c2 < CC; c2++) acc += g_T[oq * CC + c2] * g_Wf[ok * CC + c2];
    acc += g_bias[ok] * g_u[oq] + g_bias[oq] * g_u[ok] + (float)HW * g_bias[oq] * g_bias[ok];
    attn[d][e] = acc / (nq[d] * nk[e]);
    __syncthreads();
    float g1 = gating[h], g2 = gating[NHEAD + h];
    float acc2 = 0.f;
#pragma unroll
    for (int e2 = 0; e2 < 32; e2++)
        acc2 += attn[d][e2] * (g1 * mn_w[e * 32 + e2] + g2 * mn_w[(32 + e) * 32 + e2]);
    g_gmc[(h * 32 + d) * 32 + e] = __float2bfloat16(acc2);
}

// ---------------- fused kernel: 192x64 tiles, 3 GEMMs + softmax ------------------
// smem: XH[64][200]bf16 @0, CD[64][200]bf16 @25600, TS[64][197]f32 @51200 = 101632 B
__global__ __launch_bounds__(256, 2) void k_fused(const float* __restrict__ x,
                                                  const float* __restrict__ cond,
                                                  float* __restrict__ out) {
    extern __shared__ __align__(16) char smr[];
    unsigned short* XH = (unsigned short*)(smr);
    unsigned short* CD = (unsigned short*)(smr + 25600);
    float* TS = (float*)(smr + 51200);
    int tid = threadIdx.x;
    int p0 = blockIdx.x * 64;
    int warp = tid >> 5, lane = tid & 31, gid = lane >> 2, tig = lane & 3;
    int m0 = (warp >> 1) * 48, n0 = (warp & 1) * 32;

    // ---- stage xhat (bf16) and cond (bf16), pixel-major [n][c] ----
#pragma unroll
    for (int q = tid; q < 1536; q += 256) {
        int c  = (q >> 4) * 2;
        int n4 = (q & 15) * 4;
        float4 mu4 = *(const float4*)(g_mu + p0 + n4);
        float4 rs4 = *(const float4*)(g_rstd + p0 + n4);
        float4 xa = *(const float4*)(x + c * HW + p0 + n4);
        float4 xb = *(const float4*)(x + (c + 1) * HW + p0 + n4);
        float4 ca = *(const float4*)(cond + c * HW + p0 + n4);
        float4 cb = *(const float4*)(cond + (c + 1) * HW + p0 + n4);
        float mus[4] = {mu4.x, mu4.y, mu4.z, mu4.w};
        float rss[4] = {rs4.x, rs4.y, rs4.z, rs4.w};
        float xas[4] = {xa.x, xa.y, xa.z, xa.w};
        float xbs[4] = {xb.x, xb.y, xb.z, xb.w};
        float cas[4] = {ca.x, ca.y, ca.z, ca.w};
        float cbs[4] = {cb.x, cb.y, cb.z, cb.w};
#pragma unroll
        for (int j = 0; j < 4; j++) {
            __nv_bfloat162 hx = __floats2bfloat162_rn((xas[j] - mus[j]) * rss[j],
                                                      (xbs[j] - mus[j]) * rss[j]);
            *(unsigned*)&XH[(n4 + j) * 200 + c] = *(unsigned*)&hx;
            __nv_bfloat162 hc = __floats2bfloat162_rn(cas[j], cbs[j]);
            *(unsigned*)&CD[(n4 + j) * 200 + c] = *(unsigned*)&hc;
        }
    }
    __syncthreads();

    // ---- GEMM1: v = Wv @ xhat (accv in regs) ----
    float accv[3][4][4];
#pragma unroll
    for (int f = 0; f < 3; f++)
#pragma unroll
        for (int g = 0; g < 4; g++)
#pragma unroll
            for (int r = 0; r < 4; r++) accv[f][g][r] = 0.f;
#pragma unroll
    for (int kk = 0; kk < CC; kk += 32) {
#pragma unroll
        for (int ks = 0; ks < 2; ks++) {
            int kl = ks * 16 + 2 * tig;
            unsigned a[3][4];
#pragma unroll
            for (int f = 0; f < 3; f++) {
                int r = m0 + f * 16 + gid;
                a[f][0] = *(const unsigned*)&g_Wvb[r * CC + kk + kl];
                a[f][1] = *(const unsigned*)&g_Wvb[(r + 8) * CC + kk + kl];
                a[f][2] = *(const unsigned*)&g_Wvb[r * CC + kk + kl + 8];
                a[f][3] = *(const unsigned*)&g_Wvb[(r + 8) * CC + kk + kl + 8];
            }
#pragma unroll
            for (int g = 0; g < 4; g++) {
                int n = n0 + g * 8 + gid;
                unsigned bb[2];
                bb[0] = *(const unsigned*)&XH[n * 200 + kk + kl];
                bb[1] = *(const unsigned*)&XH[n * 200 + kk + kl + 8];
#pragma unroll
                for (int f = 0; f < 3; f++) mma16816(accv[f][g], a[f], bb);
            }
        }
    }

    // ---- GEMM2 (f-wise, block-diag gm): t = mi * (v + bias), folded into accv ----
#pragma unroll
    for (int f = 0; f < 3; f++) {
        float accm[4][4];
#pragma unroll
        for (int g = 0; g < 4; g++)
#pragma unroll
            for (int r = 0; r < 4; r++) accm[g][r] = 0.f;
        int row16 = m0 + f * 16;
        int kkf = (row16 >> 5) << 5;
#pragma unroll
        for (int ks = 0; ks < 2; ks++) {
            int kl = ks * 16 + 2 * tig;
            unsigned a[4];
            int r = row16 + gid;
            a[0] = *(const unsigned*)&g_gmc[r * 32 + kl];
            a[1] = *(const unsigned*)&g_gmc[(r + 8) * 32 + kl];
            a[2] = *(const unsigned*)&g_gmc[r * 32 + kl + 8];
            a[3] = *(const unsigned*)&g_gmc[(r + 8) * 32 + kl + 8];
#pragma unroll
            for (int g = 0; g < 4; g++) {
                int n = n0 + g * 8 + gid;
                unsigned bb[2];
                bb[0] = *(const unsigned*)&CD[n * 200 + kkf + kl];
                bb[1] = *(const unsigned*)&CD[n * 200 + kkf + kl + 8];
                mma16816(accm[g], a, bb);
            }
        }
        float bv0 = g_bias[384 + row16 + gid];
        float bv1 = g_bias[384 + row16 + gid + 8];
#pragma unroll
        for (int g = 0; g < 4; g++) {
            accv[f][g][0] = accm[g][0] * (accv[f][g][0] + bv0);
            accv[f][g][1] = accm[g][1] * (accv[f][g][1] + bv0);
            accv[f][g][2] = accm[g][2] * (accv[f][g][2] + bv1);
            accv[f][g][3] = accm[g][3] * (accv[f][g][3] + bv1);
        }
    }

    // ---- t -> TS ----
#pragma unroll
    for (int f = 0; f < 3; f++) {
        int m = m0 + f * 16 + gid;
#pragma unroll
        for (int g = 0; g < 4; g++) {
            int n = n0 + g * 8 + 2 * tig;
            TS[n * TSS + m]           = accv[f][g][0];
            TS[(n + 1) * TSS + m]     = accv[f][g][1];
            TS[n * TSS + m + 8]       = accv[f][g][2];
            TS[(n + 1) * TSS + m + 8] = accv[f][g][3];
        }
    }
    __syncthreads();

    // ---- softmax over head-dim per pixel; probs (bf16) -> XH ----
    for (int task = tid; task < 384; task += 256) {
        int h = task >> 6, n = task & 63;
        int base = n * TSS + h * 32;
        float t[32];
        float mx = -1e30f;
#pragma unroll
        for (int d = 0; d < 32; d++) {
            float v = TS[base + d];
            t[d] = v;
            mx = fmaxf(mx, v);
        }
        float s = 0.f;
#pragma unroll
        for (int d = 0; d < 32; d++) { float e = __expf(t[d] - mx); t[d] = e; s += e; }
        float inv = 1.f / s;
#pragma unroll
        for (int d2 = 0; d2 < 16; d2++) {
            __nv_bfloat162 hp = __floats2bfloat162_rn(t[2 * d2] * inv, t[2 * d2 + 1] * inv);
            *(unsigned*)&XH[n * 200 + h * 32 + 2 * d2] = *(unsigned*)&hp;
        }
    }
    __syncthreads();

    // ---- GEMM3: out = proj @ probs + x ----
    float acc[3][4][4];
#pragma unroll
    for (int f = 0; f < 3; f++)
#pragma unroll
        for (int g = 0; g < 4; g++)
#pragma unroll
            for (int r = 0; r < 4; r++) acc[f][g][r] = 0.f;
#pragma unroll
    for (int kk = 0; kk < CC; kk += 32) {
#pragma unroll
        for (int ks = 0; ks < 2; ks++) {
            int kl = ks * 16 + 2 * tig;
            unsigned a[3][4];
#pragma unroll
            for (int f = 0; f < 3; f++) {
                int r = m0 + f * 16 + gid;
                a[f][0] = *(const unsigned*)&g_Wpb[r * CC + kk + kl];
                a[f][1] = *(const unsigned*)&g_Wpb[(r + 8) * CC + kk + kl];
                a[f][2] = *(const unsigned*)&g_Wpb[r * CC + kk + kl + 8];
                a[f][3] = *(const unsigned*)&g_Wpb[(r + 8) * CC + kk + kl + 8];
            }
#pragma unroll
            for (int g = 0; g < 4; g++) {
                int n = n0 + g * 8 + gid;
                unsigned bb[2];
                bb[0] = *(const unsigned*)&XH[n * 200 + kk + kl];
                bb[1] = *(const unsigned*)&XH[n * 200 + kk + kl + 8];
#pragma unroll
                for (int f = 0; f < 3; f++) mma16816(acc[f][g], a[f], bb);
            }
        }
    }
#pragma unroll
    for (int f = 0; f < 3; f++) {
        int m = m0 + f * 16 + gid;
#pragma unroll
        for (int g = 0; g < 4; g++) {
            int n = n0 + g * 8 + 2 * tig;
            float2 r0 = *(const float2*)(x + m * HW + p0 + n);
            float2 r1 = *(const float2*)(x + (m + 8) * HW + p0 + n);
            float2 o0 = make_float2(acc[f][g][0] + r0.x, acc[f][g][1] + r0.y);
            float2 o1 = make_float2(acc[f][g][2] + r1.x, acc[f][g][3] + r1.y);
            *(float2*)(out + m * HW + p0 + n) = o0;
            *(float2*)(out + (m + 8) * HW + p0 + n) = o1;
        }
    }
}

// ---------------- launch ----------------
extern "C" void kernel_launch(void* const* d_in, const int* in_sizes, int n_in,
                              void* d_out, int out_size) {
    const float* x      = (const float*)d_in[0];
    const float* cond   = (const float*)d_in[1];
    const float* ln_g   = (const float*)d_in[2];
    const float* ln_b   = (const float*)d_in[3];
    const float* pre_w  = (const float*)d_in[4];
    const float* pre_b  = (const float*)d_in[5];
    const float* qkv_w  = (const float*)d_in[6];
    const float* mn_w   = (const float*)d_in[7];
    const float* gating = (const float*)d_in[8];
    const float* proj_w = (const float*)d_in[9];
    float* out = (float*)d_out;

    cudaFuncSetAttribute(k_fused, cudaFuncAttributeMaxDynamicSharedMemorySize, 101632);
    cudaFuncSetAttribute(k_gram, cudaFuncAttributeMaxDynamicSharedMemorySize, 55296);

    k_stats<<<HW / 256, 256>>>(x, proj_w);                  // 1 (+zero +cvt)
    k_fold<<<576, CC>>>(qkv_w, pre_w, ln_g, ln_b, pre_b);   // 2
    k_gram<<<304, 256, 55296>>>(x);                         // 3
    k_T<<<384, CC>>>();                                     // 4
    k_gm<<<NHEAD, 1024>>>(mn_w, gating);                    // 5
    k_fused<<<HW / 64, 256, 101632>>>(x, cond, out);        // 6
}

// round 10
// speedup vs baseline: 1.0931x; 1.0931x over previous
#include <cuda_runtime.h>
#include <cuda_bf16.h>
#include <math.h>

#define HW 200704
#define CC 192
#define NHEAD 6

// ---------------- scratch ----------------
__device__ float g_mu[HW];
__device__ float g_rstd[HW];
__device__ float g_Wf[576 * CC];
__device__ float g_bias[576];
__device__ float g_G[CC * CC];
__device__ float g_s[CC];
__device__ float g_T[384 * CC];
__device__ float g_u[384];
__device__ __align__(16) __nv_bfloat16 g_Wvb[CC * CC];   // v rows of folded weight, bf16
__device__ __align__(16) __nv_bfloat16 g_Wpb[CC * CC];   // proj_w bf16
__device__ __align__(16) __nv_bfloat16 g_gmc[CC * 32];   // per-head gm blocks, compact [192][32]

// ---------------- mma helper ----------------
__device__ __forceinline__ void mma16816(float* c, const unsigned* a, const unsigned* b) {
    asm volatile(
        "mma.sync.aligned.m16n8k16.row.col.f32.bf16.bf16.f32 "
        "{%0,%1,%2,%3},{%4,%5,%6,%7},{%8,%9},{%0,%1,%2,%3};\n"
        : "+f"(c[0]), "+f"(c[1]), "+f"(c[2]), "+f"(c[3])
        : "r"(a[0]), "r"(a[1]), "r"(a[2]), "r"(a[3]), "r"(b[0]), "r"(b[1]));
}

// ---------------- LN stats + zero accumulators + proj_w bf16 convert -------------
__global__ void k_stats(const float* __restrict__ x, const float* __restrict__ proj_w) {
    int i = blockIdx.x * 256 + threadIdx.x;
    if (i < CC * CC) { g_G[i] = 0.f; g_Wpb[i] = __float2bfloat16(proj_w[i]); }
    if (i < CC) g_s[i] = 0.f;
    int p = i;
    float s = 0.f, ss = 0.f;
#pragma unroll 8
    for (int c = 0; c < CC; c++) {
        float v = x[c * HW + p];
        s += v; ss += v * v;
    }
    float mu  = s * (1.f / CC);
    float var = ss * (1.f / CC) - mu * mu;
    g_mu[p]   = mu;
    g_rstd[p] = rsqrtf(var + 1e-5f);
}

// ---------------- fold weights ----------------
__global__ void k_fold(const float* __restrict__ qkv_w, const float* __restrict__ pre_w,
                       const float* __restrict__ ln_g, const float* __restrict__ ln_b,
                       const float* __restrict__ pre_b) {
    int o = blockIdx.x, j = threadIdx.x;
    float w2 = 0.f;
#pragma unroll 4
    for (int c = 0; c < CC; c++) w2 += qkv_w[o * CC + c] * pre_w[c * CC + j];
    float wf = w2 * ln_g[j];
    g_Wf[o * CC + j] = wf;
    if (o >= 384) g_Wvb[(o - 384) * CC + j] = __float2bfloat16(wf);
    __shared__ float s2[CC];
    s2[j] = w2 * ln_b[j] + qkv_w[o * CC + j] * pre_b[j];
    __syncthreads();
    if (j < 64) s2[j] += s2[j + 64] + s2[j + 128];
    __syncthreads();
    if (j < 32) {
        float b = s2[j] + s2[j + 32];
#pragma unroll
        for (int off = 16; off > 0; off >>= 1) b += __shfl_down_sync(0xffffffffu, b, off);
        if (j == 0) g_bias[o] = b;
    }
}

// ---------------- Gram of xhat: persistent, 64-pixel tiles, full 192x192 ---------
#define NT64 (HW / 64)
__global__ __launch_bounds__(256) void k_gram(const float* __restrict__ x) {
    extern __shared__ __align__(16) unsigned short xs[];   // [2][CC][72]
    int tid = threadIdx.x;
    int warp = tid >> 5, lane = tid & 31, gid = lane >> 2, tig = lane & 3;
    int m0 = (warp & 3) * 48;
    int n0 = (warp >> 2) * 96;
    float acc[3][12][4];
#pragma unroll
    for (int f = 0; f < 3; f++)
#pragma unroll
        for (int g = 0; g < 12; g++)
#pragma unroll
            for (int r = 0; r < 4; r++) acc[f][g][r] = 0.f;
    float srow[12];
#pragma unroll
    for (int i = 0; i < 12; i++) srow[i] = 0.f;

    auto load_half = [&](int t, int b, int h) {
        int p0 = t * 64;
#pragma unroll
        for (int i = 0; i < 6; i++) {
            int q = tid + 256 * (h * 6 + i);
            int c = q >> 4, seg = q & 15;
            int p = p0 + seg * 4;
            float4 xv = *(const float4*)(x + c * HW + p);
            float4 m4 = *(const float4*)(g_mu + p);
            float4 r4 = *(const float4*)(g_rstd + p);
            float h0 = (xv.x - m4.x) * r4.x;
            float h1 = (xv.y - m4.y) * r4.y;
            float h2 = (xv.z - m4.z) * r4.z;
            float h3 = (xv.w - m4.w) * r4.w;
            __nv_bfloat162 lo = __floats2bfloat162_rn(h0, h1);
            __nv_bfloat162 hi = __floats2bfloat162_rn(h2, h3);
            uint2 u;
            u.x = *(unsigned*)&lo;
            u.y = *(unsigned*)&hi;
            *(uint2*)(xs + (b * CC + c) * 72 + seg * 4) = u;
            srow[h * 6 + i] += h0 + h1 + h2 + h3;
        }
    };

    int t = blockIdx.x;
    int iter = 0;
    load_half(t, 0, 0);
    load_half(t, 0, 1);
    __syncthreads();
    while (t < NT64) {
        int b = iter & 1;
        int tn = t + gridDim.x;
        if (tn < NT64) { load_half(tn, b ^ 1, 0); load_half(tn, b ^ 1, 1); }
#pragma unroll
        for (int ks = 0; ks < 4; ks++) {
            int kl = ks * 16 + 2 * tig;
            unsigned a[3][4];
#pragma unroll
            for (int f = 0; f < 3; f++) {
                int r = m0 + f * 16 + gid;
                a[f][0] = *(const unsigned*)&xs[(b * CC + r) * 72 + kl];
                a[f][1] = *(const unsigned*)&xs[(b * CC + r + 8) * 72 + kl];
                a[f][2] = *(const unsigned*)&xs[(b * CC + r) * 72 + kl + 8];
                a[f][3] = *(const unsigned*)&xs[(b * CC + r + 8) * 72 + kl + 8];
            }
#pragma unroll
            for (int g = 0; g < 12; g++) {
                int n = n0 + g * 8 + gid;
                unsigned bb[2];
                bb[0] = *(const unsigned*)&xs[(b * CC + n) * 72 + kl];
                bb[1] = *(const unsigned*)&xs[(b * CC + n) * 72 + kl + 8];
#pragma unroll
                for (int f = 0; f < 3; f++) mma16816(acc[f][g], a[f], bb);
            }
        }
        __syncthreads();
        t = tn; iter++;
    }
#pragma unroll
    for (int f = 0; f < 3; f++) {
        int m = m0 + f * 16 + gid;
#pragma unroll
        for (int g = 0; g < 12; g++) {
            int n = n0 + g * 8 + 2 * tig;
            atomicAdd(&g_G[m * CC + n],           acc[f][g][0]);
            atomicAdd(&g_G[m * CC + n + 1],       acc[f][g][1]);
            atomicAdd(&g_G[(m + 8) * CC + n],     acc[f][g][2]);
            atomicAdd(&g_G[(m + 8) * CC + n + 1], acc[f][g][3]);
        }
    }
#pragma unroll
    for (int i = 0; i < 12; i++) atomicAdd(&g_s[(tid + 256 * i) >> 4], srow[i]);
}

// ---------------- T = W_{q,k} @ G ; u = W_{q,k} @ s (parallel, 384 blocks) -------
__global__ void k_T() {
    int o = blockIdx.x, j = threadIdx.x;
    float acc = 0.f;
#pragma unroll 4
    for (int c = 0; c < CC; c++) acc += g_Wf[o * CC + c] * g_G[c * CC + j];
    g_T[o * CC + j] = acc;
    __shared__ float sh[CC];
    sh[j] = g_Wf[o * CC + j] * g_s[j];
    __syncthreads();
    if (j < 64) sh[j] += sh[j + 64] + sh[j + 128];
    __syncthreads();
    if (j < 32) {
        float a = sh[j] + sh[j + 32];
#pragma unroll
        for (int off = 16; off > 0; off >>= 1) a += __shfl_down_sync(0xffffffffu, a, off);
        if (j == 0) g_u[o] = a;
    }
}

// ---------------- attn -> mn -> gating -> gm (compact bf16) ----------------
__global__ __launch_bounds__(1024) void k_gm(const float* __restrict__ mn_w,
                                             const float* __restrict__ gating) {
    int h = blockIdx.x, tid = threadIdx.x;
    int d = tid >> 5, e = tid & 31;
    __shared__ float attn[32][33];
    __shared__ float nq[32], nk[32];
    if (tid < 64) {
        int o = (tid < 32) ? (h * 32 + tid) : (CC + h * 32 + (tid - 32));
        float acc = 0.f;
        for (int c2 = 0; c2 < CC; c2++) acc += g_T[o * CC + c2] * g_Wf[o * CC + c2];
        float b = g_bias[o];
        acc += 2.f * b * g_u[o] + (float)HW * b * b;
        float nval = fmaxf(sqrtf(fmaxf(acc, 0.f)), 1e-12f);
        if (tid < 32) nq[tid] = nval; else nk[tid - 32] = nval;
    }
    __syncthreads();
    int oq = h * 32 + d, ok = CC + h * 32 + e;
    float acc = 0.f;
    for (int c2 = 0; c2 < CC; c2++) acc += g_T[oq * CC + c2] * g_Wf[ok * CC + c2];
    acc += g_bias[ok] * g_u[oq] + g_bias[oq] * g_u[ok] + (float)HW * g_bias[oq] * g_bias[ok];
    attn[d][e] = acc / (nq[d] * nk[e]);
    __syncthreads();
    float g1 = gating[h], g2 = gating[NHEAD + h];
    float acc2 = 0.f;
#pragma unroll
    for (int e2 = 0; e2 < 32; e2++)
        acc2 += attn[d][e2] * (g1 * mn_w[e * 32 + e2] + g2 * mn_w[(32 + e) * 32 + e2]);
    g_gmc[(h * 32 + d) * 32 + e] = __float2bfloat16(acc2);
}

// ---------------- fused kernel: 192x64 tiles, 3 GEMMs + vectorized softmax -------
// smem: XH[64][200]bf16 @0, CD[64][200]bf16 @25600, TS[64][196]f32 @51200 = 101376 B
__global__ __launch_bounds__(256, 2) void k_fused(const float* __restrict__ x,
                                                  const float* __restrict__ cond,
                                                  float* __restrict__ out) {
    extern __shared__ __align__(16) char smr[];
    unsigned short* XH = (unsigned short*)(smr);
    unsigned short* CD = (unsigned short*)(smr + 25600);
    float* TS = (float*)(smr + 51200);
    int tid = threadIdx.x;
    int p0 = blockIdx.x * 64;
    int warp = tid >> 5, lane = tid & 31, gid = lane >> 2, tig = lane & 3;
    int m0 = (warp >> 1) * 48, n0 = (warp & 1) * 32;

    // ---- stage xhat (bf16) and cond (bf16), pixel-major [n][c] ----
#pragma unroll
    for (int q = tid; q < 1536; q += 256) {
        int c  = (q >> 4) * 2;
        int n4 = (q & 15) * 4;
        float4 mu4 = *(const float4*)(g_mu + p0 + n4);
        float4 rs4 = *(const float4*)(g_rstd + p0 + n4);
        float4 xa = *(const float4*)(x + c * HW + p0 + n4);
        float4 xb = *(const float4*)(x + (c + 1) * HW + p0 + n4);
        float4 ca = *(const float4*)(cond + c * HW + p0 + n4);
        float4 cb = *(const float4*)(cond + (c + 1) * HW + p0 + n4);
        float mus[4] = {mu4.x, mu4.y, mu4.z, mu4.w};
        float rss[4] = {rs4.x, rs4.y, rs4.z, rs4.w};
        float xas[4] = {xa.x, xa.y, xa.z, xa.w};
        float xbs[4] = {xb.x, xb.y, xb.z, xb.w};
        float cas[4] = {ca.x, ca.y, ca.z, ca.w};
        float cbs[4] = {cb.x, cb.y, cb.z, cb.w};
#pragma unroll
        for (int j = 0; j < 4; j++) {
            __nv_bfloat162 hx = __floats2bfloat162_rn((xas[j] - mus[j]) * rss[j],
                                                      (xbs[j] - mus[j]) * rss[j]);
            *(unsigned*)&XH[(n4 + j) * 200 + c] = *(unsigned*)&hx;
            __nv_bfloat162 hc = __floats2bfloat162_rn(cas[j], cbs[j]);
            *(unsigned*)&CD[(n4 + j) * 200 + c] = *(unsigned*)&hc;
        }
    }
    __syncthreads();

    // ---- GEMM1: v = Wv @ xhat (accv in regs) ----
    float accv[3][4][4];
#pragma unroll
    for (int f = 0; f < 3; f++)
#pragma unroll
        for (int g = 0; g < 4; g++)
#pragma unroll
            for (int r = 0; r < 4; r++) accv[f][g][r] = 0.f;
#pragma unroll
    for (int kk = 0; kk < CC; kk += 32) {
#pragma unroll
        for (int ks = 0; ks < 2; ks++) {
            int kl = ks * 16 + 2 * tig;
            unsigned a[3][4];
#pragma unroll
            for (int f = 0; f < 3; f++) {
                int r = m0 + f * 16 + gid;
                a[f][0] = *(const unsigned*)&g_Wvb[r * CC + kk + kl];
                a[f][1] = *(const unsigned*)&g_Wvb[(r + 8) * CC + kk + kl];
                a[f][2] = *(const unsigned*)&g_Wvb[r * CC + kk + kl + 8];
                a[f][3] = *(const unsigned*)&g_Wvb[(r + 8) * CC + kk + kl + 8];
            }
#pragma unroll
            for (int g = 0; g < 4; g++) {
                int n = n0 + g * 8 + gid;
                unsigned bb[2];
                bb[0] = *(const unsigned*)&XH[n * 200 + kk + kl];
                bb[1] = *(const unsigned*)&XH[n * 200 + kk + kl + 8];
#pragma unroll
                for (int f = 0; f < 3; f++) mma16816(accv[f][g], a[f], bb);
            }
        }
    }

    // ---- GEMM2 (f-wise, block-diag gm): t = mi * (v + bias), folded into accv ----
#pragma unroll
    for (int f = 0; f < 3; f++) {
        float accm[4][4];
#pragma unroll
        for (int g = 0; g < 4; g++)
#pragma unroll
            for (int r = 0; r < 4; r++) accm[g][r] = 0.f;
        int row16 = m0 + f * 16;
        int kkf = (row16 >> 5) << 5;
#pragma unroll
        for (int ks = 0; ks < 2; ks++) {
            int kl = ks * 16 + 2 * tig;
            unsigned a[4];
            int r = row16 + gid;
            a[0] = *(const unsigned*)&g_gmc[r * 32 + kl];
            a[1] = *(const unsigned*)&g_gmc[(r + 8) * 32 + kl];
            a[2] = *(const unsigned*)&g_gmc[r * 32 + kl + 8];
            a[3] = *(const unsigned*)&g_gmc[(r + 8) * 32 + kl + 8];
#pragma unroll
            for (int g = 0; g < 4; g++) {
                int n = n0 + g * 8 + gid;
                unsigned bb[2];
                bb[0] = *(const unsigned*)&CD[n * 200 + kkf + kl];
                bb[1] = *(const unsigned*)&CD[n * 200 + kkf + kl + 8];
                mma16816(accm[g], a, bb);
            }
        }
        float bv0 = g_bias[384 + row16 + gid];
        float bv1 = g_bias[384 + row16 + gid + 8];
#pragma unroll
        for (int g = 0; g < 4; g++) {
            accv[f][g][0] = accm[g][0] * (accv[f][g][0] + bv0);
            accv[f][g][1] = accm[g][1] * (accv[f][g][1] + bv0);
            accv[f][g][2] = accm[g][2] * (accv[f][g][2] + bv1);
            accv[f][g][3] = accm[g][3] * (accv[f][g][3] + bv1);
        }
    }

    // ---- t -> TS ----
#pragma unroll
    for (int f = 0; f < 3; f++) {
        int m = m0 + f * 16 + gid;
#pragma unroll
        for (int g = 0; g < 4; g++) {
            int n = n0 + g * 8 + 2 * tig;
            TS[n * 196 + m]           = accv[f][g][0];
            TS[(n + 1) * 196 + m]     = accv[f][g][1];
            TS[n * 196 + m + 8]       = accv[f][g][2];
            TS[(n + 1) * 196 + m + 8] = accv[f][g][3];
        }
    }
    __syncthreads();

    // ---- softmax over head-dim per pixel (vectorized LDS.128/STS.128) ----
    for (int task = tid; task < 384; task += 256) {
        int h = task >> 6, n = task & 63;
        const float* tb = TS + n * 196 + h * 32;
        float4 t4[8];
#pragma unroll
        for (int k = 0; k < 8; k++) t4[k] = *(const float4*)(tb + 4 * k);
        float mx = -1e30f;
#pragma unroll
        for (int k = 0; k < 8; k++)
            mx = fmaxf(mx, fmaxf(fmaxf(t4[k].x, t4[k].y), fmaxf(t4[k].z, t4[k].w)));
        float s = 0.f;
#pragma unroll
        for (int k = 0; k < 8; k++) {
            t4[k].x = __expf(t4[k].x - mx); t4[k].y = __expf(t4[k].y - mx);
            t4[k].z = __expf(t4[k].z - mx); t4[k].w = __expf(t4[k].w - mx);
            s += t4[k].x + t4[k].y + t4[k].z + t4[k].w;
        }
        float inv = 1.f / s;
        unsigned short* xb = XH + n * 200 + h * 32;
#pragma unroll
        for (int j = 0; j < 4; j++) {
            __nv_bfloat162 q0 = __floats2bfloat162_rn(t4[2 * j].x * inv, t4[2 * j].y * inv);
            __nv_bfloat162 q1 = __floats2bfloat162_rn(t4[2 * j].z * inv, t4[2 * j].w * inv);
            __nv_bfloat162 q2 = __floats2bfloat162_rn(t4[2 * j + 1].x * inv, t4[2 * j + 1].y * inv);
            __nv_bfloat162 q3 = __floats2bfloat162_rn(t4[2 * j + 1].z * inv, t4[2 * j + 1].w * inv);
            uint4 u;
            u.x = *(unsigned*)&q0; u.y = *(unsigned*)&q1;
            u.z = *(unsigned*)&q2; u.w = *(unsigned*)&q3;
            *(uint4*)(xb + j * 8) = u;
        }
    }
    __syncthreads();

    // ---- GEMM3: out = proj @ probs + x ----
    float acc[3][4][4];
#pragma unroll
    for (int f = 0; f < 3; f++)
#pragma unroll
        for (int g = 0; g < 4; g++)
#pragma unroll
            for (int r = 0; r < 4; r++) acc[f][g][r] = 0.f;
#pragma unroll
    for (int kk = 0; kk < CC; kk += 32) {
#pragma unroll
        for (int ks = 0; ks < 2; ks++) {
            int kl = ks * 16 + 2 * tig;
            unsigned a[3][4];
#pragma unroll
            for (int f = 0; f < 3; f++) {
                int r = m0 + f * 16 + gid;
                a[f][0] = *(const unsigned*)&g_Wpb[r * CC + kk + kl];
                a[f][1] = *(const unsigned*)&g_Wpb[(r + 8) * CC + kk + kl];
                a[f][2] = *(const unsigned*)&g_Wpb[r * CC + kk + kl + 8];
                a[f][3] = *(const unsigned*)&g_Wpb[(r + 8) * CC + kk + kl + 8];
            }
#pragma unroll
            for (int g = 0; g < 4; g++) {
                int n = n0 + g * 8 + gid;
                unsigned bb[2];
                bb[0] = *(const unsigned*)&XH[n * 200 + kk + kl];
                bb[1] = *(const unsigned*)&XH[n * 200 + kk + kl + 8];
#pragma unroll
                for (int f = 0; f < 3; f++) mma16816(acc[f][g], a[f], bb);
            }
        }
    }
#pragma unroll
    for (int f = 0; f < 3; f++) {
        int m = m0 + f * 16 + gid;
#pragma unroll
        for (int g = 0; g < 4; g++) {
            int n = n0 + g * 8 + 2 * tig;
            float2 r0 = *(const float2*)(x + m * HW + p0 + n);
            float2 r1 = *(const float2*)(x + (m + 8) * HW + p0 + n);
            float2 o0 = make_float2(acc[f][g][0] + r0.x, acc[f][g][1] + r0.y);
            float2 o1 = make_float2(acc[f][g][2] + r1.x, acc[f][g][3] + r1.y);
            *(float2*)(out + m * HW + p0 + n) = o0;
            *(float2*)(out + (m + 8) * HW + p0 + n) = o1;
        }
    }
}

// ---------------- launch ----------------
extern "C" void kernel_launch(void* const* d_in, const int* in_sizes, int n_in,
                              void* d_out, int out_size) {
    const float* x      = (const float*)d_in[0];
    const float* cond   = (const float*)d_in[1];
    const float* ln_g   = (const float*)d_in[2];
    const float* ln_b   = (const float*)d_in[3];
    const float* pre_w  = (const float*)d_in[4];
    const float* pre_b  = (const float*)d_in[5];
    const float* qkv_w  = (const float*)d_in[6];
    const float* mn_w   = (const float*)d_in[7];
    const float* gating = (const float*)d_in[8];
    const float* proj_w = (const float*)d_in[9];
    float* out = (float*)d_out;

    cudaFuncSetAttribute(k_fused, cudaFuncAttributeMaxDynamicSharedMemorySize, 101376);
    cudaFuncSetAttribute(k_gram, cudaFuncAttributeMaxDynamicSharedMemorySize, 55296);

    k_stats<<<HW / 256, 256>>>(x, proj_w);                  // 1 (+zero +cvt)
    k_fold<<<576, CC>>>(qkv_w, pre_w, ln_g, ln_b, pre_b);   // 2
    k_gram<<<152, 256, 55296>>>(x);                         // 3
    k_T<<<384, CC>>>();                                     // 4
    k_gm<<<NHEAD, 1024>>>(mn_w, gating);                    // 5
    k_fused<<<HW / 64, 256, 101376>>>(x, cond, out);        // 6
}

// round 11
// speedup vs baseline: 1.0960x; 1.0026x over previous
#include <cuda_runtime.h>
#include <cuda_bf16.h>
#include <math.h>

#define HW 200704
#define CC 192
#define NHEAD 6

// ---------------- scratch ----------------
__device__ float g_mu[HW];
__device__ float g_rstd[HW];
__device__ float g_Wf[576 * CC];
__device__ float g_bias[576];
__device__ float g_G[CC * CC];
__device__ float g_s[CC];
__device__ float g_T[384 * CC];
__device__ float g_u[384];
__device__ __align__(16) __nv_bfloat16 g_Wvb[CC * CC];   // v rows of folded weight, bf16
__device__ __align__(16) __nv_bfloat16 g_Wpb[CC * CC];   // proj_w bf16
__device__ __align__(16) __nv_bfloat16 g_gmc[CC * 32];   // per-head gm blocks, compact [192][32]

// ---------------- mma helper ----------------
__device__ __forceinline__ void mma16816(float* c, const unsigned* a, const unsigned* b) {
    asm volatile(
        "mma.sync.aligned.m16n8k16.row.col.f32.bf16.bf16.f32 "
        "{%0,%1,%2,%3},{%4,%5,%6,%7},{%8,%9},{%0,%1,%2,%3};\n"
        : "+f"(c[0]), "+f"(c[1]), "+f"(c[2]), "+f"(c[3])
        : "r"(a[0]), "r"(a[1]), "r"(a[2]), "r"(a[3]), "r"(b[0]), "r"(b[1]));
}

// ---------------- LN stats + zero accumulators + proj_w bf16 convert -------------
__global__ void k_stats(const float* __restrict__ x, const float* __restrict__ proj_w) {
    int i = blockIdx.x * 256 + threadIdx.x;
    if (i < CC * CC) { g_G[i] = 0.f; g_Wpb[i] = __float2bfloat16(proj_w[i]); }
    if (i < CC) g_s[i] = 0.f;
    int p = i;
    float s = 0.f, ss = 0.f;
#pragma unroll 8
    for (int c = 0; c < CC; c++) {
        float v = x[c * HW + p];
        s += v; ss += v * v;
    }
    float mu  = s * (1.f / CC);
    float var = ss * (1.f / CC) - mu * mu;
    g_mu[p]   = mu;
    g_rstd[p] = rsqrtf(var + 1e-5f);
}

// ---------------- fold weights ----------------
__global__ void k_fold(const float* __restrict__ qkv_w, const float* __restrict__ pre_w,
                       const float* __restrict__ ln_g, const float* __restrict__ ln_b,
                       const float* __restrict__ pre_b) {
    int o = blockIdx.x, j = threadIdx.x;
    float w2 = 0.f;
#pragma unroll 4
    for (int c = 0; c < CC; c++) w2 += qkv_w[o * CC + c] * pre_w[c * CC + j];
    float wf = w2 * ln_g[j];
    g_Wf[o * CC + j] = wf;
    if (o >= 384) g_Wvb[(o - 384) * CC + j] = __float2bfloat16(wf);
    __shared__ float s2[CC];
    s2[j] = w2 * ln_b[j] + qkv_w[o * CC + j] * pre_b[j];
    __syncthreads();
    if (j < 64) s2[j] += s2[j + 64] + s2[j + 128];
    __syncthreads();
    if (j < 32) {
        float b = s2[j] + s2[j + 32];
#pragma unroll
        for (int off = 16; off > 0; off >>= 1) b += __shfl_down_sync(0xffffffffu, b, off);
        if (j == 0) g_bias[o] = b;
    }
}

// ---------------- Gram of xhat: persistent, 64-pixel tiles, 384 threads ----------
// 12 warps: 4 m-groups x 3 n-groups; warp tile 48x64 (acc[3][8][4])
#define NT64 (HW / 64)
__global__ __launch_bounds__(384) void k_gram(const float* __restrict__ x) {
    extern __shared__ __align__(16) unsigned short xs[];   // [2][CC][72]
    int tid = threadIdx.x;
    int warp = tid >> 5, lane = tid & 31, gid = lane >> 2, tig = lane & 3;
    int m0 = (warp & 3) * 48;
    int n0 = (warp >> 2) * 64;
    float acc[3][8][4];
#pragma unroll
    for (int f = 0; f < 3; f++)
#pragma unroll
        for (int g = 0; g < 8; g++)
#pragma unroll
            for (int r = 0; r < 4; r++) acc[f][g][r] = 0.f;
    float srow[8];
#pragma unroll
    for (int i = 0; i < 8; i++) srow[i] = 0.f;

    auto load_half = [&](int t, int b, int h) {
        int p0 = t * 64;
#pragma unroll
        for (int i = 0; i < 4; i++) {
            int q = tid + 384 * (h * 4 + i);
            int c = q >> 4, seg = q & 15;
            int p = p0 + seg * 4;
            float4 xv = *(const float4*)(x + c * HW + p);
            float4 m4 = *(const float4*)(g_mu + p);
            float4 r4 = *(const float4*)(g_rstd + p);
            float h0 = (xv.x - m4.x) * r4.x;
            float h1 = (xv.y - m4.y) * r4.y;
            float h2 = (xv.z - m4.z) * r4.z;
            float h3 = (xv.w - m4.w) * r4.w;
            __nv_bfloat162 lo = __floats2bfloat162_rn(h0, h1);
            __nv_bfloat162 hi = __floats2bfloat162_rn(h2, h3);
            uint2 u;
            u.x = *(unsigned*)&lo;
            u.y = *(unsigned*)&hi;
            *(uint2*)(xs + (b * CC + c) * 72 + seg * 4) = u;
            srow[h * 4 + i] += h0 + h1 + h2 + h3;
        }
    };

    int t = blockIdx.x;
    int iter = 0;
    load_half(t, 0, 0);
    load_half(t, 0, 1);
    __syncthreads();
    while (t < NT64) {
        int b = iter & 1;
        int tn = t + gridDim.x;
        if (tn < NT64) { load_half(tn, b ^ 1, 0); load_half(tn, b ^ 1, 1); }
#pragma unroll
        for (int ks = 0; ks < 4; ks++) {
            int kl = ks * 16 + 2 * tig;
            unsigned a[3][4];
#pragma unroll
            for (int f = 0; f < 3; f++) {
                int r = m0 + f * 16 + gid;
                a[f][0] = *(const unsigned*)&xs[(b * CC + r) * 72 + kl];
                a[f][1] = *(const unsigned*)&xs[(b * CC + r + 8) * 72 + kl];
                a[f][2] = *(const unsigned*)&xs[(b * CC + r) * 72 + kl + 8];
                a[f][3] = *(const unsigned*)&xs[(b * CC + r + 8) * 72 + kl + 8];
            }
#pragma unroll
            for (int g = 0; g < 8; g++) {
                int n = n0 + g * 8 + gid;
                unsigned bb[2];
                bb[0] = *(const unsigned*)&xs[(b * CC + n) * 72 + kl];
                bb[1] = *(const unsigned*)&xs[(b * CC + n) * 72 + kl + 8];
#pragma unroll
                for (int f = 0; f < 3; f++) mma16816(acc[f][g], a[f], bb);
            }
        }
        __syncthreads();
        t = tn; iter++;
    }
#pragma unroll
    for (int f = 0; f < 3; f++) {
        int m = m0 + f * 16 + gid;
#pragma unroll
        for (int g = 0; g < 8; g++) {
            int n = n0 + g * 8 + 2 * tig;
            atomicAdd(&g_G[m * CC + n],           acc[f][g][0]);
            atomicAdd(&g_G[m * CC + n + 1],       acc[f][g][1]);
            atomicAdd(&g_G[(m + 8) * CC + n],     acc[f][g][2]);
            atomicAdd(&g_G[(m + 8) * CC + n + 1], acc[f][g][3]);
        }
    }
#pragma unroll
    for (int i = 0; i < 8; i++) atomicAdd(&g_s[(tid + 384 * i) >> 4], srow[i]);
}

// ---------------- T = W_{q,k} @ G ; u = W_{q,k} @ s (parallel, 384 blocks) -------
__global__ void k_T() {
    int o = blockIdx.x, j = threadIdx.x;
    float acc = 0.f;
#pragma unroll 4
    for (int c = 0; c < CC; c++) acc += g_Wf[o * CC + c] * g_G[c * CC + j];
    g_T[o * CC + j] = acc;
    __shared__ float sh[CC];
    sh[j] = g_Wf[o * CC + j] * g_s[j];
    __syncthreads();
    if (j < 64) sh[j] += sh[j + 64] + sh[j + 128];
    __syncthreads();
    if (j < 32) {
        float a = sh[j] + sh[j + 32];
#pragma unroll
        for (int off = 16; off > 0; off >>= 1) a += __shfl_down_sync(0xffffffffu, a, off);
        if (j == 0) g_u[o] = a;
    }
}

// ---------------- attn -> mn -> gating -> gm (compact bf16) ----------------
__global__ __launch_bounds__(1024) void k_gm(const float* __restrict__ mn_w,
                                             const float* __restrict__ gating) {
    int h = blockIdx.x, tid = threadIdx.x;
    int d = tid >> 5, e = tid & 31;
    __shared__ float attn[32][33];
    __shared__ float nq[32], nk[32];
    if (tid < 64) {
        int o = (tid < 32) ? (h * 32 + tid) : (CC + h * 32 + (tid - 32));
        float acc = 0.f;
        for (int c2 = 0; c2 < CC; c2++) acc += g_T[o * CC + c2] * g_Wf[o * CC + c2];
        float b = g_bias[o];
        acc += 2.f * b * g_u[o] + (float)HW * b * b;
        float nval = fmaxf(sqrtf(fmaxf(acc, 0.f)), 1e-12f);
        if (tid < 32) nq[tid] = nval; else nk[tid - 32] = nval;
    }
    __syncthreads();
    int oq = h * 32 + d, ok = CC + h * 32 + e;
    float acc = 0.f;
    for (int c2 = 0; c2 < CC; c2++) acc += g_T[oq * CC + c2] * g_Wf[ok * CC + c2];
    acc += g_bias[ok] * g_u[oq] + g_bias[oq] * g_u[ok] + (float)HW * g_bias[oq] * g_bias[ok];
    attn[d][e] = acc / (nq[d] * nk[e]);
    __syncthreads();
    float g1 = gating[h], g2 = gating[NHEAD + h];
    float acc2 = 0.f;
#pragma unroll
    for (int e2 = 0; e2 < 32; e2++)
        acc2 += attn[d][e2] * (g1 * mn_w[e * 32 + e2] + g2 * mn_w[(32 + e) * 32 + e2]);
    g_gmc[(h * 32 + d) * 32 + e] = __float2bfloat16(acc2);
}

// ---------------- fused kernel: 192x64 tiles, 3 GEMMs + vectorized softmax -------
// smem: XH[64][200]bf16 @0, CD[64][200]bf16 @25600, TS[64][196]f32 @51200 = 101376 B
__global__ __launch_bounds__(256, 2) void k_fused(const float* __restrict__ x,
                                                  const float* __restrict__ cond,
                                                  float* __restrict__ out) {
    extern __shared__ __align__(16) char smr[];
    unsigned short* XH = (unsigned short*)(smr);
    unsigned short* CD = (unsigned short*)(smr + 25600);
    float* TS = (float*)(smr + 51200);
    int tid = threadIdx.x;
    int p0 = blockIdx.x * 64;
    int warp = tid >> 5, lane = tid & 31, gid = lane >> 2, tig = lane & 3;
    int m0 = (warp >> 1) * 48, n0 = (warp & 1) * 32;

    // ---- stage xhat (bf16) and cond (bf16), pixel-major [n][c] ----
#pragma unroll
    for (int q = tid; q < 1536; q += 256) {
        int c  = (q >> 4) * 2;
        int n4 = (q & 15) * 4;
        float4 mu4 = *(const float4*)(g_mu + p0 + n4);
        float4 rs4 = *(const float4*)(g_rstd + p0 + n4);
        float4 xa = *(const float4*)(x + c * HW + p0 + n4);
        float4 xb = *(const float4*)(x + (c + 1) * HW + p0 + n4);
        float4 ca = *(const float4*)(cond + c * HW + p0 + n4);
        float4 cb = *(const float4*)(cond + (c + 1) * HW + p0 + n4);
        float mus[4] = {mu4.x, mu4.y, mu4.z, mu4.w};
        float rss[4] = {rs4.x, rs4.y, rs4.z, rs4.w};
        float xas[4] = {xa.x, xa.y, xa.z, xa.w};
        float xbs[4] = {xb.x, xb.y, xb.z, xb.w};
        float cas[4] = {ca.x, ca.y, ca.z, ca.w};
        float cbs[4] = {cb.x, cb.y, cb.z, cb.w};
#pragma unroll
        for (int j = 0; j < 4; j++) {
            __nv_bfloat162 hx = __floats2bfloat162_rn((xas[j] - mus[j]) * rss[j],
                                                      (xbs[j] - mus[j]) * rss[j]);
            *(unsigned*)&XH[(n4 + j) * 200 + c] = *(unsigned*)&hx;
            __nv_bfloat162 hc = __floats2bfloat162_rn(cas[j], cbs[j]);
            *(unsigned*)&CD[(n4 + j) * 200 + c] = *(unsigned*)&hc;
        }
    }
    __syncthreads();

    // ---- GEMM1: v = Wv @ xhat (accv in regs) ----
    float accv[3][4][4];
#pragma unroll
    for (int f = 0; f < 3; f++)
#pragma unroll
        for (int g = 0; g < 4; g++)
#pragma unroll
            for (int r = 0; r < 4; r++) accv[f][g][r] = 0.f;
#pragma unroll
    for (int kk = 0; kk < CC; kk += 32) {
#pragma unroll
        for (int ks = 0; ks < 2; ks++) {
            int kl = ks * 16 + 2 * tig;
            unsigned a[3][4];
#pragma unroll
            for (int f = 0; f < 3; f++) {
                int r = m0 + f * 16 + gid;
                a[f][0] = *(const unsigned*)&g_Wvb[r * CC + kk + kl];
                a[f][1] = *(const unsigned*)&g_Wvb[(r + 8) * CC + kk + kl];
                a[f][2] = *(const unsigned*)&g_Wvb[r * CC + kk + kl + 8];
                a[f][3] = *(const unsigned*)&g_Wvb[(r + 8) * CC + kk + kl + 8];
            }
#pragma unroll
            for (int g = 0; g < 4; g++) {
                int n = n0 + g * 8 + gid;
                unsigned bb[2];
                bb[0] = *(const unsigned*)&XH[n * 200 + kk + kl];
                bb[1] = *(const unsigned*)&XH[n * 200 + kk + kl + 8];
#pragma unroll
                for (int f = 0; f < 3; f++) mma16816(accv[f][g], a[f], bb);
            }
        }
    }

    // ---- GEMM2 (f-wise, block-diag gm): t = mi * (v + bias), folded into accv ----
#pragma unroll
    for (int f = 0; f < 3; f++) {
        float accm[4][4];
#pragma unroll
        for (int g = 0; g < 4; g++)
#pragma unroll
            for (int r = 0; r < 4; r++) accm[g][r] = 0.f;
        int row16 = m0 + f * 16;
        int kkf = (row16 >> 5) << 5;
#pragma unroll
        for (int ks = 0; ks < 2; ks++) {
            int kl = ks * 16 + 2 * tig;
            unsigned a[4];
            int r = row16 + gid;
            a[0] = *(const unsigned*)&g_gmc[r * 32 + kl];
            a[1] = *(const unsigned*)&g_gmc[(r + 8) * 32 + kl];
            a[2] = *(const unsigned*)&g_gmc[r * 32 + kl + 8];
            a[3] = *(const unsigned*)&g_gmc[(r + 8) * 32 + kl + 8];
#pragma unroll
            for (int g = 0; g < 4; g++) {
                int n = n0 + g * 8 + gid;
                unsigned bb[2];
                bb[0] = *(const unsigned*)&CD[n * 200 + kkf + kl];
                bb[1] = *(const unsigned*)&CD[n * 200 + kkf + kl + 8];
                mma16816(accm[g], a, bb);
            }
        }
        float bv0 = g_bias[384 + row16 + gid];
        float bv1 = g_bias[384 + row16 + gid + 8];
#pragma unroll
        for (int g = 0; g < 4; g++) {
            accv[f][g][0] = accm[g][0] * (accv[f][g][0] + bv0);
            accv[f][g][1] = accm[g][1] * (accv[f][g][1] + bv0);
            accv[f][g][2] = accm[g][2] * (accv[f][g][2] + bv1);
            accv[f][g][3] = accm[g][3] * (accv[f][g][3] + bv1);
        }
    }

    // ---- t -> TS ----
#pragma unroll
    for (int f = 0; f < 3; f++) {
        int m = m0 + f * 16 + gid;
#pragma unroll
        for (int g = 0; g < 4; g++) {
            int n = n0 + g * 8 + 2 * tig;
            TS[n * 196 + m]           = accv[f][g][0];
            TS[(n + 1) * 196 + m]     = accv[f][g][1];
            TS[n * 196 + m + 8]       = accv[f][g][2];
            TS[(n + 1) * 196 + m + 8] = accv[f][g][3];
        }
    }
    __syncthreads();

    // ---- softmax over head-dim per pixel (vectorized LDS.128/STS.128) ----
    for (int task = tid; task < 384; task += 256) {
        int h = task >> 6, n = task & 63;
        const float* tb = TS + n * 196 + h * 32;
        float4 t4[8];
#pragma unroll
        for (int k = 0; k < 8; k++) t4[k] = *(const float4*)(tb + 4 * k);
        float mx = -1e30f;
#pragma unroll
        for (int k = 0; k < 8; k++)
            mx = fmaxf(mx, fmaxf(fmaxf(t4[k].x, t4[k].y), fmaxf(t4[k].z, t4[k].w)));
        float s = 0.f;
#pragma unroll
        for (int k = 0; k < 8; k++) {
            t4[k].x = __expf(t4[k].x - mx); t4[k].y = __expf(t4[k].y - mx);
            t4[k].z = __expf(t4[k].z - mx); t4[k].w = __expf(t4[k].w - mx);
            s += t4[k].x + t4[k].y + t4[k].z + t4[k].w;
        }
        float inv = 1.f / s;
        unsigned short* xb = XH + n * 200 + h * 32;
#pragma unroll
        for (int j = 0; j < 4; j++) {
            __nv_bfloat162 q0 = __floats2bfloat162_rn(t4[2 * j].x * inv, t4[2 * j].y * inv);
            __nv_bfloat162 q1 = __floats2bfloat162_rn(t4[2 * j].z * inv, t4[2 * j].w * inv);
            __nv_bfloat162 q2 = __floats2bfloat162_rn(t4[2 * j + 1].x * inv, t4[2 * j + 1].y * inv);
            __nv_bfloat162 q3 = __floats2bfloat162_rn(t4[2 * j + 1].z * inv, t4[2 * j + 1].w * inv);
            uint4 u;
            u.x = *(unsigned*)&q0; u.y = *(unsigned*)&q1;
            u.z = *(unsigned*)&q2; u.w = *(unsigned*)&q3;
            *(uint4*)(xb + j * 8) = u;
        }
    }
    __syncthreads();

    // ---- GEMM3: out = proj @ probs + x ----
    float acc[3][4][4];
#pragma unroll
    for (int f = 0; f < 3; f++)
#pragma unroll
        for (int g = 0; g < 4; g++)
#pragma unroll
            for (int r = 0; r < 4; r++) acc[f][g][r] = 0.f;
#pragma unroll
    for (int kk = 0; kk < CC; kk += 32) {
#pragma unroll
        for (int ks = 0; ks < 2; ks++) {
            int kl = ks * 16 + 2 * tig;
            unsigned a[3][4];
#pragma unroll
            for (int f = 0; f < 3; f++) {
                int r = m0 + f * 16 + gid;
                a[f][0] = *(const unsigned*)&g_Wpb[r * CC + kk + kl];
                a[f][1] = *(const unsigned*)&g_Wpb[(r + 8) * CC + kk + kl];
                a[f][2] = *(const unsigned*)&g_Wpb[r * CC + kk + kl + 8];
                a[f][3] = *(const unsigned*)&g_Wpb[(r + 8) * CC + kk + kl + 8];
            }
#pragma unroll
            for (int g = 0; g < 4; g++) {
                int n = n0 + g * 8 + gid;
                unsigned bb[2];
                bb[0] = *(const unsigned*)&XH[n * 200 + kk + kl];
                bb[1] = *(const unsigned*)&XH[n * 200 + kk + kl + 8];
#pragma unroll
                for (int f = 0; f < 3; f++) mma16816(acc[f][g], a[f], bb);
            }
        }
    }
#pragma unroll
    for (int f = 0; f < 3; f++) {
        int m = m0 + f * 16 + gid;
#pragma unroll
        for (int g = 0; g < 4; g++) {
            int n = n0 + g * 8 + 2 * tig;
            float2 r0 = *(const float2*)(x + m * HW + p0 + n);
            float2 r1 = *(const float2*)(x + (m + 8) * HW + p0 + n);
            float2 o0 = make_float2(acc[f][g][0] + r0.x, acc[f][g][1] + r0.y);
            float2 o1 = make_float2(acc[f][g][2] + r1.x, acc[f][g][3] + r1.y);
            *(float2*)(out + m * HW + p0 + n) = o0;
            *(float2*)(out + (m + 8) * HW + p0 + n) = o1;
        }
    }
}

// ---------------- launch ----------------
extern "C" void kernel_launch(void* const* d_in, const int* in_sizes, int n_in,
                              void* d_out, int out_size) {
    const float* x      = (const float*)d_in[0];
    const float* cond   = (const float*)d_in[1];
    const float* ln_g   = (const float*)d_in[2];
    const float* ln_b   = (const float*)d_in[3];
    const float* pre_w  = (const float*)d_in[4];
    const float* pre_b  = (const float*)d_in[5];
    const float* qkv_w  = (const float*)d_in[6];
    const float* mn_w   = (const float*)d_in[7];
    const float* gating = (const float*)d_in[8];
    const float* proj_w = (const float*)d_in[9];
    float* out = (float*)d_out;

    cudaFuncSetAttribute(k_fused, cudaFuncAttributeMaxDynamicSharedMemorySize, 101376);
    cudaFuncSetAttribute(k_gram, cudaFuncAttributeMaxDynamicSharedMemorySize, 55296);

    k_stats<<<HW / 256, 256>>>(x, proj_w);                  // 1 (+zero +cvt)
    k_fold<<<576, CC>>>(qkv_w, pre_w, ln_g, ln_b, pre_b);   // 2
    k_gram<<<148, 384, 55296>>>(x);                         // 3
    k_T<<<384, CC>>>();                                     // 4
    k_gm<<<NHEAD, 1024>>>(mn_w, gating);                    // 5
    k_fused<<<HW / 64, 256, 101376>>>(x, cond, out);        // 6
}

// round 12
// speedup vs baseline: 1.3831x; 1.2619x over previous
#include <cuda_runtime.h>
#include <cuda_bf16.h>
#include <math.h>

#define HW 200704
#define CC 192
#define NHEAD 6

// ---------------- scratch ----------------
__device__ float g_mu[HW];
__device__ float g_rstd[HW];
__device__ float g_Wf[576 * CC];
__device__ float g_bias[576];
__device__ float g_G[CC * CC];
__device__ float g_s[CC];
__device__ float g_T[384 * CC];
__device__ float g_u[384];
__device__ __align__(16) __nv_bfloat16 g_Wvf[CC * CC];   // v weight, mma-fragment order
__device__ __align__(16) __nv_bfloat16 g_Wpf[CC * CC];   // proj weight, mma-fragment order
__device__ __align__(16) __nv_bfloat16 g_gmc[CC * 32];   // per-head gm blocks, compact [192][32]

// fragment scatter index: A m16n8k16 row-major bf16 fragment layout
// lane = gid*4+tig; uint4 = {W[r][k0..k0+1], W[r+8][k0..], W[r][k0+8..], W[r+8][k0+8..]}
__device__ __forceinline__ int frag_idx(int o, int j) {
    int mt = o >> 4, kt = j >> 4;
    int om = o & 15, jm = j & 15;
    int gid = om & 7, hi_m = om >> 3;
    int tig = (jm & 7) >> 1, hi_k = jm >> 3, par = jm & 1;
    int lane = gid * 4 + tig;
    return (((kt * 12 + mt) * 32 + lane) << 3) + ((hi_m + 2 * hi_k) << 1) + par;
}

// ---------------- mma helper ----------------
__device__ __forceinline__ void mma16816(float* c, const unsigned* a, const unsigned* b) {
    asm volatile(
        "mma.sync.aligned.m16n8k16.row.col.f32.bf16.bf16.f32 "
        "{%0,%1,%2,%3},{%4,%5,%6,%7},{%8,%9},{%0,%1,%2,%3};\n"
        : "+f"(c[0]), "+f"(c[1]), "+f"(c[2]), "+f"(c[3])
        : "r"(a[0]), "r"(a[1]), "r"(a[2]), "r"(a[3]), "r"(b[0]), "r"(b[1]));
}

// ---------------- LN stats + zero accumulators + proj_w fragment convert ---------
__global__ void k_stats(const float* __restrict__ x, const float* __restrict__ proj_w) {
    int i = blockIdx.x * 256 + threadIdx.x;
    if (i < CC * CC) {
        g_G[i] = 0.f;
        int o = i / CC, j = i - o * CC;
        g_Wpf[frag_idx(o, j)] = __float2bfloat16(proj_w[i]);
    }
    if (i < CC) g_s[i] = 0.f;
    int p = i;
    float s = 0.f, ss = 0.f;
#pragma unroll 8
    for (int c = 0; c < CC; c++) {
        float v = x[c * HW + p];
        s += v; ss += v * v;
    }
    float mu  = s * (1.f / CC);
    float var = ss * (1.f / CC) - mu * mu;
    g_mu[p]   = mu;
    g_rstd[p] = rsqrtf(var + 1e-5f);
}

// ---------------- fold weights ----------------
__global__ void k_fold(const float* __restrict__ qkv_w, const float* __restrict__ pre_w,
                       const float* __restrict__ ln_g, const float* __restrict__ ln_b,
                       const float* __restrict__ pre_b) {
    int o = blockIdx.x, j = threadIdx.x;
    float w2 = 0.f;
#pragma unroll 4
    for (int c = 0; c < CC; c++) w2 += qkv_w[o * CC + c] * pre_w[c * CC + j];
    float wf = w2 * ln_g[j];
    g_Wf[o * CC + j] = wf;
    if (o >= 384) g_Wvf[frag_idx(o - 384, j)] = __float2bfloat16(wf);
    __shared__ float s2[CC];
    s2[j] = w2 * ln_b[j] + qkv_w[o * CC + j] * pre_b[j];
    __syncthreads();
    if (j < 64) s2[j] += s2[j + 64] + s2[j + 128];
    __syncthreads();
    if (j < 32) {
        float b = s2[j] + s2[j + 32];
#pragma unroll
        for (int off = 16; off > 0; off >>= 1) b += __shfl_down_sync(0xffffffffu, b, off);
        if (j == 0) g_bias[o] = b;
    }
}

// ---------------- Gram of xhat: persistent, 64-pixel tiles, 384 threads ----------
#define NT64 (HW / 64)
__global__ __launch_bounds__(384) void k_gram(const float* __restrict__ x) {
    extern __shared__ __align__(16) unsigned short xs[];   // [2][CC][72]
    int tid = threadIdx.x;
    int warp = tid >> 5, lane = tid & 31, gid = lane >> 2, tig = lane & 3;
    int m0 = (warp & 3) * 48;
    int n0 = (warp >> 2) * 64;
    float acc[3][8][4];
#pragma unroll
    for (int f = 0; f < 3; f++)
#pragma unroll
        for (int g = 0; g < 8; g++)
#pragma unroll
            for (int r = 0; r < 4; r++) acc[f][g][r] = 0.f;
    float srow[8];
#pragma unroll
    for (int i = 0; i < 8; i++) srow[i] = 0.f;

    auto load_half = [&](int t, int b, int h) {
        int p0 = t * 64;
#pragma unroll
        for (int i = 0; i < 4; i++) {
            int q = tid + 384 * (h * 4 + i);
            int c = q >> 4, seg = q & 15;
            int p = p0 + seg * 4;
            float4 xv = *(const float4*)(x + c * HW + p);
            float4 m4 = *(const float4*)(g_mu + p);
            float4 r4 = *(const float4*)(g_rstd + p);
            float h0 = (xv.x - m4.x) * r4.x;
            float h1 = (xv.y - m4.y) * r4.y;
            float h2 = (xv.z - m4.z) * r4.z;
            float h3 = (xv.w - m4.w) * r4.w;
            __nv_bfloat162 lo = __floats2bfloat162_rn(h0, h1);
            __nv_bfloat162 hi = __floats2bfloat162_rn(h2, h3);
            uint2 u;
            u.x = *(unsigned*)&lo;
            u.y = *(unsigned*)&hi;
            *(uint2*)(xs + (b * CC + c) * 72 + seg * 4) = u;
            srow[h * 4 + i] += h0 + h1 + h2 + h3;
        }
    };

    int t = blockIdx.x;
    int iter = 0;
    load_half(t, 0, 0);
    load_half(t, 0, 1);
    __syncthreads();
    while (t < NT64) {
        int b = iter & 1;
        int tn = t + gridDim.x;
        if (tn < NT64) { load_half(tn, b ^ 1, 0); load_half(tn, b ^ 1, 1); }
#pragma unroll
        for (int ks = 0; ks < 4; ks++) {
            int kl = ks * 16 + 2 * tig;
            unsigned a[3][4];
#pragma unroll
            for (int f = 0; f < 3; f++) {
                int r = m0 + f * 16 + gid;
                a[f][0] = *(const unsigned*)&xs[(b * CC + r) * 72 + kl];
                a[f][1] = *(const unsigned*)&xs[(b * CC + r + 8) * 72 + kl];
                a[f][2] = *(const unsigned*)&xs[(b * CC + r) * 72 + kl + 8];
                a[f][3] = *(const unsigned*)&xs[(b * CC + r + 8) * 72 + kl + 8];
            }
#pragma unroll
            for (int g = 0; g < 8; g++) {
                int n = n0 + g * 8 + gid;
                unsigned bb[2];
                bb[0] = *(const unsigned*)&xs[(b * CC + n) * 72 + kl];
                bb[1] = *(const unsigned*)&xs[(b * CC + n) * 72 + kl + 8];
#pragma unroll
                for (int f = 0; f < 3; f++) mma16816(acc[f][g], a[f], bb);
            }
        }
        __syncthreads();
        t = tn; iter++;
    }
#pragma unroll
    for (int f = 0; f < 3; f++) {
        int m = m0 + f * 16 + gid;
#pragma unroll
        for (int g = 0; g < 8; g++) {
            int n = n0 + g * 8 + 2 * tig;
            atomicAdd(&g_G[m * CC + n],           acc[f][g][0]);
            atomicAdd(&g_G[m * CC + n + 1],       acc[f][g][1]);
            atomicAdd(&g_G[(m + 8) * CC + n],     acc[f][g][2]);
            atomicAdd(&g_G[(m + 8) * CC + n + 1], acc[f][g][3]);
        }
    }
#pragma unroll
    for (int i = 0; i < 8; i++) atomicAdd(&g_s[(tid + 384 * i) >> 4], srow[i]);
}

// ---------------- T = W_{q,k} @ G ; u = W_{q,k} @ s (parallel, 384 blocks) -------
__global__ void k_T() {
    int o = blockIdx.x, j = threadIdx.x;
    float acc = 0.f;
#pragma unroll 4
    for (int c = 0; c < CC; c++) acc += g_Wf[o * CC + c] * g_G[c * CC + j];
    g_T[o * CC + j] = acc;
    __shared__ float sh[CC];
    sh[j] = g_Wf[o * CC + j] * g_s[j];
    __syncthreads();
    if (j < 64) sh[j] += sh[j + 64] + sh[j + 128];
    __syncthreads();
    if (j < 32) {
        float a = sh[j] + sh[j + 32];
#pragma unroll
        for (int off = 16; off > 0; off >>= 1) a += __shfl_down_sync(0xffffffffu, a, off);
        if (j == 0) g_u[o] = a;
    }
}

// ---------------- attn -> mn -> gating -> gm (compact bf16) ----------------
__global__ __launch_bounds__(1024) void k_gm(const float* __restrict__ mn_w,
                                             const float* __restrict__ gating) {
    int h = blockIdx.x, tid = threadIdx.x;
    int d = tid >> 5, e = tid & 31;
    __shared__ float attn[32][33];
    __shared__ float nq[32], nk[32];
    if (tid < 64) {
        int o = (tid < 32) ? (h * 32 + tid) : (CC + h * 32 + (tid - 32));
        float acc = 0.f;
        for (int c2 = 0; c2 < CC; c2++) acc += g_T[o * CC + c2] * g_Wf[o * CC + c2];
        float b = g_bias[o];
        acc += 2.f * b * g_u[o] + (float)HW * b * b;
        float nval = fmaxf(sqrtf(fmaxf(acc, 0.f)), 1e-12f);
        if (tid < 32) nq[tid] = nval; else nk[tid - 32] = nval;
    }
    __syncthreads();
    int oq = h * 32 + d, ok = CC + h * 32 + e;
    float acc = 0.f;
    for (int c2 = 0; c2 < CC; c2++) acc += g_T[oq * CC + c2] * g_Wf[ok * CC + c2];
    acc += g_bias[ok] * g_u[oq] + g_bias[oq] * g_u[ok] + (float)HW * g_bias[oq] * g_bias[ok];
    attn[d][e] = acc / (nq[d] * nk[e]);
    __syncthreads();
    float g1 = gating[h], g2 = gating[NHEAD + h];
    float acc2 = 0.f;
#pragma unroll
    for (int e2 = 0; e2 < 32; e2++)
        acc2 += attn[d][e2] * (g1 * mn_w[e * 32 + e2] + g2 * mn_w[(32 + e) * 32 + e2]);
    g_gmc[(h * 32 + d) * 32 + e] = __float2bfloat16(acc2);
}

// ---------------- fused kernel: fragment-order weight loads (LDG.128) ------------
// smem: XH[64][200]bf16 @0, CD[64][200]bf16 @25600, TS[64][196]f32 @51200 = 101376 B
__global__ __launch_bounds__(256, 2) void k_fused(const float* __restrict__ x,
                                                  const float* __restrict__ cond,
                                                  float* __restrict__ out) {
    extern __shared__ __align__(16) char smr[];
    unsigned short* XH = (unsigned short*)(smr);
    unsigned short* CD = (unsigned short*)(smr + 25600);
    float* TS = (float*)(smr + 51200);
    int tid = threadIdx.x;
    int p0 = blockIdx.x * 64;
    int warp = tid >> 5, lane = tid & 31, gid = lane >> 2, tig = lane & 3;
    int m0 = (warp >> 1) * 48, n0 = (warp & 1) * 32;
    int mt0 = (warp >> 1) * 3;

    // ---- stage xhat (bf16) and cond (bf16), pixel-major [n][c] ----
#pragma unroll
    for (int q = tid; q < 1536; q += 256) {
        int c  = (q >> 4) * 2;
        int n4 = (q & 15) * 4;
        float4 mu4 = *(const float4*)(g_mu + p0 + n4);
        float4 rs4 = *(const float4*)(g_rstd + p0 + n4);
        float4 xa = *(const float4*)(x + c * HW + p0 + n4);
        float4 xb = *(const float4*)(x + (c + 1) * HW + p0 + n4);
        float4 ca = *(const float4*)(cond + c * HW + p0 + n4);
        float4 cb = *(const float4*)(cond + (c + 1) * HW + p0 + n4);
        float mus[4] = {mu4.x, mu4.y, mu4.z, mu4.w};
        float rss[4] = {rs4.x, rs4.y, rs4.z, rs4.w};
        float xas[4] = {xa.x, xa.y, xa.z, xa.w};
        float xbs[4] = {xb.x, xb.y, xb.z, xb.w};
        float cas[4] = {ca.x, ca.y, ca.z, ca.w};
        float cbs[4] = {cb.x, cb.y, cb.z, cb.w};
#pragma unroll
        for (int j = 0; j < 4; j++) {
            __nv_bfloat162 hx = __floats2bfloat162_rn((xas[j] - mus[j]) * rss[j],
                                                      (xbs[j] - mus[j]) * rss[j]);
            *(unsigned*)&XH[(n4 + j) * 200 + c] = *(unsigned*)&hx;
            __nv_bfloat162 hc = __floats2bfloat162_rn(cas[j], cbs[j]);
            *(unsigned*)&CD[(n4 + j) * 200 + c] = *(unsigned*)&hc;
        }
    }
    __syncthreads();

    // ---- GEMM1: v = Wv @ xhat (fragment-order LDG.128 weights) ----
    float accv[3][4][4];
#pragma unroll
    for (int f = 0; f < 3; f++)
#pragma unroll
        for (int g = 0; g < 4; g++)
#pragma unroll
            for (int r = 0; r < 4; r++) accv[f][g][r] = 0.f;
#pragma unroll
    for (int kt = 0; kt < 12; kt++) {
        uint4 a[3];
#pragma unroll
        for (int f = 0; f < 3; f++)
            a[f] = *(const uint4*)&g_Wvf[(((kt * 12) + (mt0 + f)) * 32 + lane) * 8];
        int kb = kt * 16 + 2 * tig;
#pragma unroll
        for (int g = 0; g < 4; g++) {
            int n = n0 + g * 8 + gid;
            unsigned bb[2];
            bb[0] = *(const unsigned*)&XH[n * 200 + kb];
            bb[1] = *(const unsigned*)&XH[n * 200 + kb + 8];
#pragma unroll
            for (int f = 0; f < 3; f++) mma16816(accv[f][g], (const unsigned*)&a[f], bb);
        }
    }

    // ---- GEMM2 (f-wise, block-diag gm): t = mi * (v + bias), folded into accv ----
#pragma unroll
    for (int f = 0; f < 3; f++) {
        float accm[4][4];
#pragma unroll
        for (int g = 0; g < 4; g++)
#pragma unroll
            for (int r = 0; r < 4; r++) accm[g][r] = 0.f;
        int row16 = m0 + f * 16;
        int kkf = (row16 >> 5) << 5;
#pragma unroll
        for (int ks = 0; ks < 2; ks++) {
            int kl = ks * 16 + 2 * tig;
            unsigned a[4];
            int r = row16 + gid;
            a[0] = *(const unsigned*)&g_gmc[r * 32 + kl];
            a[1] = *(const unsigned*)&g_gmc[(r + 8) * 32 + kl];
            a[2] = *(const unsigned*)&g_gmc[r * 32 + kl + 8];
            a[3] = *(const unsigned*)&g_gmc[(r + 8) * 32 + kl + 8];
#pragma unroll
            for (int g = 0; g < 4; g++) {
                int n = n0 + g * 8 + gid;
                unsigned bb[2];
                bb[0] = *(const unsigned*)&CD[n * 200 + kkf + kl];
                bb[1] = *(const unsigned*)&CD[n * 200 + kkf + kl + 8];
                mma16816(accm[g], a, bb);
            }
        }
        float bv0 = g_bias[384 + row16 + gid];
        float bv1 = g_bias[384 + row16 + gid + 8];
#pragma unroll
        for (int g = 0; g < 4; g++) {
            accv[f][g][0] = accm[g][0] * (accv[f][g][0] + bv0);
            accv[f][g][1] = accm[g][1] * (accv[f][g][1] + bv0);
            accv[f][g][2] = accm[g][2] * (accv[f][g][2] + bv1);
            accv[f][g][3] = accm[g][3] * (accv[f][g][3] + bv1);
        }
    }

    // ---- t -> TS ----
#pragma unroll
    for (int f = 0; f < 3; f++) {
        int m = m0 + f * 16 + gid;
#pragma unroll
        for (int g = 0; g < 4; g++) {
            int n = n0 + g * 8 + 2 * tig;
            TS[n * 196 + m]           = accv[f][g][0];
            TS[(n + 1) * 196 + m]     = accv[f][g][1];
            TS[n * 196 + m + 8]       = accv[f][g][2];
            TS[(n + 1) * 196 + m + 8] = accv[f][g][3];
        }
    }
    __syncthreads();

    // ---- softmax over head-dim per pixel (vectorized LDS.128/STS.128) ----
    for (int task = tid; task < 384; task += 256) {
        int h = task >> 6, n = task & 63;
        const float* tb = TS + n * 196 + h * 32;
        float4 t4[8];
#pragma unroll
        for (int k = 0; k < 8; k++) t4[k] = *(const float4*)(tb + 4 * k);
        float mx = -1e30f;
#pragma unroll
        for (int k = 0; k < 8; k++)
            mx = fmaxf(mx, fmaxf(fmaxf(t4[k].x, t4[k].y), fmaxf(t4[k].z, t4[k].w)));
        float s = 0.f;
#pragma unroll
        for (int k = 0; k < 8; k++) {
            t4[k].x = __expf(t4[k].x - mx); t4[k].y = __expf(t4[k].y - mx);
            t4[k].z = __expf(t4[k].z - mx); t4[k].w = __expf(t4[k].w - mx);
            s += t4[k].x + t4[k].y + t4[k].z + t4[k].w;
        }
        float inv = 1.f / s;
        unsigned short* xb = XH + n * 200 + h * 32;
#pragma unroll
        for (int j = 0; j < 4; j++) {
            __nv_bfloat162 q0 = __floats2bfloat162_rn(t4[2 * j].x * inv, t4[2 * j].y * inv);
            __nv_bfloat162 q1 = __floats2bfloat162_rn(t4[2 * j].z * inv, t4[2 * j].w * inv);
            __nv_bfloat162 q2 = __floats2bfloat162_rn(t4[2 * j + 1].x * inv, t4[2 * j + 1].y * inv);
            __nv_bfloat162 q3 = __floats2bfloat162_rn(t4[2 * j + 1].z * inv, t4[2 * j + 1].w * inv);
            uint4 u;
            u.x = *(unsigned*)&q0; u.y = *(unsigned*)&q1;
            u.z = *(unsigned*)&q2; u.w = *(unsigned*)&q3;
            *(uint4*)(xb + j * 8) = u;
        }
    }
    __syncthreads();

    // ---- GEMM3: out = proj @ probs + x (fragment-order LDG.128 weights) ----
    float acc[3][4][4];
#pragma unroll
    for (int f = 0; f < 3; f++)
#pragma unroll
        for (int g = 0; g < 4; g++)
#pragma unroll
            for (int r = 0; r < 4; r++) acc[f][g][r] = 0.f;
#pragma unroll
    for (int kt = 0; kt < 12; kt++) {
        uint4 a[3];
#pragma unroll
        for (int f = 0; f < 3; f++)
            a[f] = *(const uint4*)&g_Wpf[(((kt * 12) + (mt0 + f)) * 32 + lane) * 8];
        int kb = kt * 16 + 2 * tig;
#pragma unroll
        for (int g = 0; g < 4; g++) {
            int n = n0 + g * 8 + gid;
            unsigned bb[2];
            bb[0] = *(const unsigned*)&XH[n * 200 + kb];
            bb[1] = *(const unsigned*)&XH[n * 200 + kb + 8];
#pragma unroll
            for (int f = 0; f < 3; f++) mma16816(acc[f][g], (const unsigned*)&a[f], bb);
        }
    }
#pragma unroll
    for (int f = 0; f < 3; f++) {
        int m = m0 + f * 16 + gid;
#pragma unroll
        for (int g = 0; g < 4; g++) {
            int n = n0 + g * 8 + 2 * tig;
            float2 r0 = *(const float2*)(x + m * HW + p0 + n);
            float2 r1 = *(const float2*)(x + (m + 8) * HW + p0 + n);
            float2 o0 = make_float2(acc[f][g][0] + r0.x, acc[f][g][1] + r0.y);
            float2 o1 = make_float2(acc[f][g][2] + r1.x, acc[f][g][3] + r1.y);
            *(float2*)(out + m * HW + p0 + n) = o0;
            *(float2*)(out + (m + 8) * HW + p0 + n) = o1;
        }
    }
}

// ---------------- launch ----------------
extern "C" void kernel_launch(void* const* d_in, const int* in_sizes, int n_in,
                              void* d_out, int out_size) {
    const float* x      = (const float*)d_in[0];
    const float* cond   = (const float*)d_in[1];
    const float* ln_g   = (const float*)d_in[2];
    const float* ln_b   = (const float*)d_in[3];
    const float* pre_w  = (const float*)d_in[4];
    const float* pre_b  = (const float*)d_in[5];
    const float* qkv_w  = (const float*)d_in[6];
    const float* mn_w   = (const float*)d_in[7];
    const float* gating = (const float*)d_in[8];
    const float* proj_w = (const float*)d_in[9];
    float* out = (float*)d_out;

    cudaFuncSetAttribute(k_fused, cudaFuncAttributeMaxDynamicSharedMemorySize, 101376);
    cudaFuncSetAttribute(k_gram, cudaFuncAttributeMaxDynamicSharedMemorySize, 55296);

    k_stats<<<HW / 256, 256>>>(x, proj_w);                  // 1 (+zero +cvt)
    k_fold<<<576, CC>>>(qkv_w, pre_w, ln_g, ln_b, pre_b);   // 2
    k_gram<<<148, 384, 55296>>>(x);                         // 3
    k_T<<<384, CC>>>();                                     // 4
    k_gm<<<NHEAD, 1024>>>(mn_w, gating);                    // 5
    k_fused<<<HW / 64, 256, 101376>>>(x, cond, out);        // 6
}